// round 13
// baseline (speedup 1.0000x reference)
#include <cuda_runtime.h>
#include <math.h>

// Problem constants (from reference)
#define NPROJS 128
#define L_DIM  1024
#define S_DIM  256
#define SPACING 4.7952
#define MU0     0.013

#define NBLOCKS 128            // measured-optimal grid: one 8-warp CTA per SM
#define NWARPS_TOTAL (NBLOCKS * 8)   // 1024 arrivals at the accumulator

// Packed accumulator: bits [0:52)  fixed-point sum (scale 2^40; total < 2^45)
//                     bits [52:64) arrival count (1024 < 2^12).
__device__ unsigned long long g_acc = 0ULL;

#define FIX_SCALE   1099511627776.0f      /* 2^40 */
#define FIX_INV     (1.0 / 1099511627776.0)
#define COUNT_ONE   (1ULL << 52)
#define SUM_MASK    ((1ULL << 52) - 1ULL)

__global__ void __launch_bounds__(256) edcc_fused_kernel(
    const float* __restrict__ projs, float base, float step,
    float* __restrict__ out)
{
    const unsigned int lane = threadIdx.x & 31u;
    const unsigned int warp = threadIdx.x >> 5;     // 0..7 -> row in block
    const unsigned int l = blockIdx.x * 8u + warp;  // row 0..1023
    const unsigned int row_f4 = l * (S_DIM / 4);

    // Two used projection slices (i=127, j=29); one warp handles row l.
    const float4* __restrict__ p4 = (const float4*)projs;
    const unsigned int ibase = 127u * (L_DIM * S_DIM / 4) + row_f4 + lane;
    const unsigned int jbase = 29u  * (L_DIM * S_DIM / 4) + row_f4 + lane;

    // Front-batch all 4 independent 16B loads (max MLP before any use)
    const float4 a0 = p4[ibase];
    const float4 a1 = p4[ibase + 32];
    const float4 b0 = p4[jbase];
    const float4 b1 = p4[jbase + 32];

    // Weights: w(e) = exp(base + e*step); base/step precomputed on host.
    // MUFU work overlaps the in-flight loads.
    const float e0 = (float)(lane * 4u);
    const float e1 = (float)((lane + 32u) * 4u);
    const float w0 = __expf(fmaf(e0,        step, base));
    const float w1 = __expf(fmaf(e0 + 1.0f, step, base));
    const float w2 = __expf(fmaf(e0 + 2.0f, step, base));
    const float w3 = __expf(fmaf(e0 + 3.0f, step, base));
    const float u0 = __expf(fmaf(e1,        step, base));
    const float u1 = __expf(fmaf(e1 + 1.0f, step, base));
    const float u2 = __expf(fmaf(e1 + 2.0f, step, base));
    const float u3 = __expf(fmaf(e1 + 3.0f, step, base));

    float vi = a0.x * w0 + a0.y * w1 + a0.z * w2 + a0.w * w3
             + a1.x * u0 + a1.y * u1 + a1.z * u2 + a1.w * u3;
    float vj = b0.x * w0 + b0.y * w1 + b0.z * w2 + b0.w * w3
             + b1.x * u0 + b1.y * u1 + b1.z * u2 + b1.w * u3;

    // Warp reduction -> P_i, P_j (two independent ladders pipeline)
    #pragma unroll
    for (int off = 16; off > 0; off >>= 1) {
        vi += __shfl_down_sync(0xFFFFFFFFu, vi, off);
        vj += __shfl_down_sync(0xFFFFFFFFu, vj, off);
    }

    // Every warp fires ONE packed atomic directly — no barrier, no smem.
    // Integer adds commute -> bitwise deterministic across replays.
    if (lane == 0) {
        // den > 0 always: inputs uniform[0,1), weights > 0.
        const float term = (2.0f / (float)NPROJS) * fabsf(vi - vj) / (vi + vj);
        const unsigned long long contrib =
            (unsigned long long)(term * FIX_SCALE) | COUNT_ONE;
        const unsigned long long old = atomicAdd(&g_acc, contrib);

        if ((old >> 52) == (unsigned long long)(NWARPS_TOTAL - 1)) {
            const unsigned long long total = (old + contrib) & SUM_MASK;
            out[0] = (float)((double)total * FIX_INV);  // mean over B=1
            g_acc = 0ULL;   // re-arm for next graph replay
        }
    }
}

extern "C" void kernel_launch(void* const* d_in, const int* in_sizes, int n_in,
                              void* d_out, int out_size)
{
    const float* projs = (const float*)d_in[0];
    float* out = (float*)d_out;

    // sigma = MU0 * tan((theta[127] - theta[29]) / 2), theta_k = 2*pi*k/128
    // Weight argument: arg(e) = sigma*SPACING*(s_start + e*SPACING)
    const double two_pi = 6.283185307179586;
    const double th_i = two_pi * 127.0 / 128.0;
    const double th_j = two_pi * 29.0 / 128.0;
    const double sigma = MU0 * tan((th_i - th_j) * 0.5);
    const double s_start = (-(double)S_DIM * SPACING + SPACING) * 0.5;
    const float base = (float)(sigma * SPACING * s_start);
    const float step = (float)(sigma * SPACING * SPACING);

    edcc_fused_kernel<<<NBLOCKS, 256>>>(projs, base, step, out);
}

// round 14
// speedup vs baseline: 1.0337x; 1.0337x over previous
#include <cuda_runtime.h>
#include <math.h>

// Problem constants (from reference)
#define NPROJS 128
#define L_DIM  1024
#define S_DIM  256
#define SPACING 4.7952f
#define MU0     0.013f

#define NBLOCKS 128            // one wave; measured-optimal grid shape
#define ROWS_PER_BLOCK 8       // one warp per row, 256 threads/block

// Packed accumulator: bits [0:56) fixed-point sum (scale 2^40),
//                     bits [56:64) arrival count. Zero at load; last
// arrival resets it for the next graph replay.
__device__ unsigned long long g_acc = 0ULL;

#define FIX_SCALE   1099511627776.0f      /* 2^40 */
#define FIX_INV     (1.0 / 1099511627776.0)
#define COUNT_ONE   (1ULL << 56)
#define SUM_MASK    ((1ULL << 56) - 1ULL)

__global__ void __launch_bounds__(256) edcc_fused_kernel(
    const float* __restrict__ projs, float sigma, float* __restrict__ out)
{
    const int lane = threadIdx.x & 31;
    const int warp = threadIdx.x >> 5;      // 0..7 -> row within block
    const int l = blockIdx.x * ROWS_PER_BLOCK + warp;

    // Two used projection slices (i=127, j=29); one warp handles row l.
    const float4* __restrict__ pi = (const float4*)(projs
        + (size_t)127 * L_DIM * S_DIM + (size_t)l * S_DIM);
    const float4* __restrict__ pj = (const float4*)(projs
        + (size_t)29  * L_DIM * S_DIM + (size_t)l * S_DIM);

    // Front-batch all 4 independent 16B loads (max MLP before any use)
    const float4 a0 = pi[lane];
    const float4 a1 = pi[lane + 32];
    const float4 b0 = pj[lane];
    const float4 b1 = pj[lane + 32];

    // Weight: w(e) = exp(sigma * s(e) * SPACING), s(e) = s_start + e*SPACING
    const float s_start = (-(float)S_DIM * SPACING + SPACING) * 0.5f;
    const float c1 = sigma * SPACING;
    const float base = c1 * s_start;
    const float step = c1 * SPACING;

    float vi, vj;
    {
        const int e0 = lane * 4;
        const float w0 = __expf(base + (float)(e0 + 0) * step);
        const float w1 = __expf(base + (float)(e0 + 1) * step);
        const float w2 = __expf(base + (float)(e0 + 2) * step);
        const float w3 = __expf(base + (float)(e0 + 3) * step);
        const int e1 = (lane + 32) * 4;
        const float u0 = __expf(base + (float)(e1 + 0) * step);
        const float u1 = __expf(base + (float)(e1 + 1) * step);
        const float u2 = __expf(base + (float)(e1 + 2) * step);
        const float u3 = __expf(base + (float)(e1 + 3) * step);

        vi = a0.x * w0 + a0.y * w1 + a0.z * w2 + a0.w * w3
           + a1.x * u0 + a1.y * u1 + a1.z * u2 + a1.w * u3;
        vj = b0.x * w0 + b0.y * w1 + b0.z * w2 + b0.w * w3
           + b1.x * u0 + b1.y * u1 + b1.z * u2 + b1.w * u3;
    }

    // Warp reduction -> P_i, P_j for this row
    #pragma unroll
    for (int off = 16; off > 0; off >>= 1) {
        vi += __shfl_down_sync(0xFFFFFFFFu, vi, off);
        vj += __shfl_down_sync(0xFFFFFFFFu, vj, off);
    }

    __shared__ float sh_terms[ROWS_PER_BLOCK];
    if (lane == 0) {
        const float den = vi + vj;
        sh_terms[warp] = (den != 0.0f)
                       ? (2.0f / (float)NPROJS) * fabsf(vi - vj) / den
                       : 0.0f;
    }
    __syncthreads();

    if (threadIdx.x == 0) {
        float bsum = 0.0f;
        #pragma unroll
        for (int k = 0; k < ROWS_PER_BLOCK; k++) bsum += sh_terms[k];

        // Fixed-point contribution + arrival count in ONE atomic.
        // Integer adds commute -> result is bitwise deterministic.
        const unsigned long long contrib =
            (unsigned long long)(bsum * FIX_SCALE) | COUNT_ONE;
        const unsigned long long old = atomicAdd(&g_acc, contrib);

        if ((old >> 56) == (unsigned long long)(NBLOCKS - 1)) {
            const unsigned long long total = (old + contrib) & SUM_MASK;
            out[0] = (float)((double)total * FIX_INV);  // mean over B=1 -> identity
            g_acc = 0ULL;   // re-arm for next graph replay (same-thread ordering)
        }
    }
}

extern "C" void kernel_launch(void* const* d_in, const int* in_sizes, int n_in,
                              void* d_out, int out_size)
{
    const float* projs = (const float*)d_in[0];
    float* out = (float*)d_out;

    // sigma = MU0 * tan((theta[127] - theta[29]) / 2), theta_k = 2*pi*k/128
    const double two_pi = 6.283185307179586;
    const double th_i = two_pi * 127.0 / 128.0;
    const double th_j = two_pi * 29.0 / 128.0;
    const float sigma = (float)((double)MU0 * tan((th_i - th_j) * 0.5));

    edcc_fused_kernel<<<NBLOCKS, 256>>>(projs, sigma, out);
}